// round 2
// baseline (speedup 1.0000x reference)
#include <cuda_runtime.h>

#define NMAX 100000
#define DD   128

// Scratch (allocation-free): ping-pong feature buffers + degree info.
__device__ float g_deg[NMAX];
__device__ float g_dinv[NMAX];
__device__ float g_h[(size_t)NMAX * DD];   // GEMM output (messages source)
__device__ float g_a[(size_t)NMAX * DD];   // aggregated layer-1 output

// ---------------------------------------------------------------------------
// Degree / normalization
// ---------------------------------------------------------------------------
__global__ void k_deg_init(int n) {
    int i = blockIdx.x * blockDim.x + threadIdx.x;
    if (i < n) g_deg[i] = 1.0f;   // self loop
}

__global__ void k_deg_count(const int* __restrict__ dst, int E) {
    int e = blockIdx.x * blockDim.x + threadIdx.x;
    if (e < E) atomicAdd(&g_deg[dst[e]], 1.0f);
}

__global__ void k_dinv(int n) {
    int i = blockIdx.x * blockDim.x + threadIdx.x;
    if (i < n) g_dinv[i] = rsqrtf(g_deg[i]);
}

// ---------------------------------------------------------------------------
// SGEMM: Y[n,128] = X[n,128] @ W[128,128]^T   (Y[r,j] = sum_k X[r,k]*W[j,k])
// Block: 128 rows x 128 cols, 256 threads, 8x8 micro-tile with stride-16 layout
// (conflict-free shared loads).
// ---------------------------------------------------------------------------
__global__ __launch_bounds__(256) void k_gemm(const float* __restrict__ X,
                                              const float* __restrict__ W,
                                              float* __restrict__ Y, int n) {
    __shared__ float xs[128][17];   // [row][k], pad 17
    __shared__ float Ws[16][129];   // [k][j],  pad 129 (W transposed in smem)

    const int tid  = threadIdx.x;
    const int tcol = tid & 15;      // 0..15
    const int trow = tid >> 4;      // 0..15
    const int br   = blockIdx.x * 128;

    float acc[8][8];
#pragma unroll
    for (int i = 0; i < 8; i++)
#pragma unroll
        for (int j = 0; j < 8; j++) acc[i][j] = 0.0f;

    for (int kt = 0; kt < 128; kt += 16) {
#pragma unroll
        for (int i = 0; i < 8; i++) {            // 2048 X elements
            int idx = tid + i * 256;
            int k = idx & 15, r = idx >> 4;
            int row = br + r;
            xs[r][k] = (row < n) ? X[(size_t)row * 128 + kt + k] : 0.0f;
        }
#pragma unroll
        for (int i = 0; i < 8; i++) {            // 2048 W elements (transposed)
            int idx = tid + i * 256;
            int k = idx & 15, j = idx >> 4;
            Ws[k][j] = W[(size_t)j * 128 + kt + k];
        }
        __syncthreads();

#pragma unroll
        for (int k = 0; k < 16; k++) {
            float a[8], b[8];
#pragma unroll
            for (int i = 0; i < 8; i++) a[i] = xs[trow + 16 * i][k];
#pragma unroll
            for (int j = 0; j < 8; j++) b[j] = Ws[k][tcol + 16 * j];
#pragma unroll
            for (int i = 0; i < 8; i++)
#pragma unroll
                for (int j = 0; j < 8; j++) acc[i][j] += a[i] * b[j];
        }
        __syncthreads();
    }

#pragma unroll
    for (int i = 0; i < 8; i++) {
        int row = br + trow + 16 * i;
        if (row < n) {
#pragma unroll
            for (int j = 0; j < 8; j++)
                Y[(size_t)row * 128 + tcol + 16 * j] = acc[i][j];
        }
    }
}

// ---------------------------------------------------------------------------
// Init aggregation buffer with self-loop term + bias + perturbation:
//   O[i,:] = dinv[i]^2 * H[i,:] + b[:] + P[i,:]
// float4-vectorized: n*32 threads.
// ---------------------------------------------------------------------------
__global__ void k_init(const float4* __restrict__ H, const float* __restrict__ bias,
                       const float4* __restrict__ P, float4* __restrict__ O, int n) {
    int idx = blockIdx.x * blockDim.x + threadIdx.x;
    if (idx >= n * 32) return;
    int row = idx >> 5;
    int c   = idx & 31;
    float di = g_dinv[row];
    float s  = di * di;
    float4 h = H[idx];
    float4 p = P[idx];
    float4 bb = ((const float4*)bias)[c];
    float4 o;
    o.x = h.x * s + bb.x + p.x;
    o.y = h.y * s + bb.y + p.y;
    o.z = h.z * s + bb.z + p.z;
    o.w = h.w * s + bb.w + p.w;
    O[idx] = o;
}

// ---------------------------------------------------------------------------
// Edge aggregation: one warp per edge; lane handles 4 consecutive floats.
//   O[dst,:] += dinv[src]*dinv[dst] * H[src,:]
// ---------------------------------------------------------------------------
__global__ void k_edge(const float4* __restrict__ H, const int* __restrict__ src,
                       const int* __restrict__ dst, float* __restrict__ O, int E) {
    int t = blockIdx.x * blockDim.x + threadIdx.x;
    int e = t >> 5;
    if (e >= E) return;
    int lane = t & 31;
    int s = __ldg(src + e);
    int d = __ldg(dst + e);
    float nrm = g_dinv[s] * g_dinv[d];
    float4 v = H[(size_t)s * 32 + lane];
    float* o = O + (size_t)d * 128 + lane * 4;
    atomicAdd(o + 0, v.x * nrm);
    atomicAdd(o + 1, v.y * nrm);
    atomicAdd(o + 2, v.z * nrm);
    atomicAdd(o + 3, v.w * nrm);
}

// ---------------------------------------------------------------------------
// Launch
// ---------------------------------------------------------------------------
extern "C" void kernel_launch(void* const* d_in, const int* in_sizes, int n_in,
                              void* d_out, int out_size) {
    const float* x  = (const float*)d_in[0];
    const int*   ei = (const int*)  d_in[1];
    const float* pf = (const float*)d_in[2];
    const float* pl = (const float*)d_in[3];
    const float* W1 = (const float*)d_in[4];
    const float* b1 = (const float*)d_in[5];
    const float* W2 = (const float*)d_in[6];
    const float* b2 = (const float*)d_in[7];
    float* out = (float*)d_out;

    const int n = in_sizes[0] / DD;
    const int E = in_sizes[1] / 2;
    const int* src = ei;
    const int* dst = ei + E;

    float* ph; float* pa;
    cudaGetSymbolAddress((void**)&ph, g_h);
    cudaGetSymbolAddress((void**)&pa, g_a);

    const int T = 256;

    // degree + dinv
    k_deg_init<<<(n + T - 1) / T, T>>>(n);
    k_deg_count<<<(E + T - 1) / T, T>>>(dst, E);
    k_dinv<<<(n + T - 1) / T, T>>>(n);

    const int gemm_blocks = (n + 127) / 128;
    const int init_blocks = (n * 32 + T - 1) / T;
    const int edge_blocks = (E + 7) / 8;   // 8 warps/block, 1 warp/edge

    // Layer 1: h = x @ W1^T ; a = A_hat * h + b1 + perturb_first
    k_gemm<<<gemm_blocks, T>>>(x, W1, ph, n);
    k_init<<<init_blocks, T>>>((const float4*)ph, b1, (const float4*)pf, (float4*)pa, n);
    k_edge<<<edge_blocks, T>>>((const float4*)ph, src, dst, pa, E);

    // Layer 2: h = a @ W2^T ; out = A_hat * h + b2 + perturb_last
    k_gemm<<<gemm_blocks, T>>>(pa, W2, ph, n);
    k_init<<<init_blocks, T>>>((const float4*)ph, b2, (const float4*)pl, (float4*)out, n);
    k_edge<<<edge_blocks, T>>>((const float4*)ph, src, dst, out, E);
}

// round 3
// speedup vs baseline: 2.9627x; 2.9627x over previous
#include <cuda_runtime.h>

#define NMAX 100064
#define EMAX 1600000
#define DD   128

// Scratch (allocation-free)
__device__ float g_dinv[NMAX];
__device__ int   g_cnt[NMAX];       // in-degree (edges only)
__device__ int   g_rowptr[NMAX];    // exclusive scan of cnt
__device__ int   g_cursor[NMAX];    // scatter cursors
__device__ int   g_col[EMAX];       // CSR column (src) indices, grouped by dst
__device__ int   g_part[1024];      // scan partials
__device__ float g_h[(size_t)NMAX * DD];   // GEMM output
__device__ float g_a[(size_t)NMAX * DD];   // layer-1 aggregated output

// ---------------------------------------------------------------------------
// Degree / CSR build
// ---------------------------------------------------------------------------
__global__ void k_zero_cnt(int n) {
    int i = blockIdx.x * blockDim.x + threadIdx.x;
    if (i < n) g_cnt[i] = 0;
}

__global__ void k_count(const int* __restrict__ dst, int E) {
    int e = blockIdx.x * blockDim.x + threadIdx.x;
    if (e < E) atomicAdd(&g_cnt[dst[e]], 1);
}

__global__ void k_dinv(int n) {
    int i = blockIdx.x * blockDim.x + threadIdx.x;
    if (i < n) g_dinv[i] = rsqrtf((float)(g_cnt[i] + 1));  // +1 self loop
}

// Level-1 scan: each 1024-thread block scans a 1024-element tile of g_cnt,
// writes EXCLUSIVE per-tile scan into g_rowptr and tile total into g_part.
__global__ __launch_bounds__(1024) void k_scan1(int n) {
    const int tid = threadIdx.x;
    const int gid = blockIdx.x * 1024 + tid;
    const int lane = tid & 31, wid = tid >> 5;
    int v = (gid < n) ? g_cnt[gid] : 0;
    int x = v;
#pragma unroll
    for (int o = 1; o < 32; o <<= 1) {
        int y = __shfl_up_sync(0xffffffffu, x, o);
        if (lane >= o) x += y;
    }
    __shared__ int wsum[32];
    if (lane == 31) wsum[wid] = x;
    __syncthreads();
    if (wid == 0) {
        int s = wsum[lane];
#pragma unroll
        for (int o = 1; o < 32; o <<= 1) {
            int y = __shfl_up_sync(0xffffffffu, s, o);
            if (lane >= o) s += y;
        }
        wsum[lane] = s;
    }
    __syncthreads();
    int incl = x + (wid > 0 ? wsum[wid - 1] : 0);
    if (gid < n) g_rowptr[gid] = incl - v;   // exclusive within tile
    if (tid == 1023) g_part[blockIdx.x] = incl;  // tile total
}

// Level-2 scan: one block, exclusive scan of up to 1024 partials in place.
__global__ __launch_bounds__(1024) void k_scan2(int nb) {
    const int tid = threadIdx.x;
    const int lane = tid & 31, wid = tid >> 5;
    int v = (tid < nb) ? g_part[tid] : 0;
    int x = v;
#pragma unroll
    for (int o = 1; o < 32; o <<= 1) {
        int y = __shfl_up_sync(0xffffffffu, x, o);
        if (lane >= o) x += y;
    }
    __shared__ int wsum[32];
    if (lane == 31) wsum[wid] = x;
    __syncthreads();
    if (wid == 0) {
        int s = wsum[lane];
#pragma unroll
        for (int o = 1; o < 32; o <<= 1) {
            int y = __shfl_up_sync(0xffffffffu, s, o);
            if (lane >= o) s += y;
        }
        wsum[lane] = s;
    }
    __syncthreads();
    int excl = x - v + (wid > 0 ? wsum[wid - 1] : 0);
    if (tid < nb) g_part[tid] = excl;
}

// Level-3: add tile offsets; initialize cursors.
__global__ __launch_bounds__(1024) void k_scan3(int n) {
    int gid = blockIdx.x * 1024 + threadIdx.x;
    if (gid < n) {
        int rp = g_rowptr[gid] + g_part[blockIdx.x];
        g_rowptr[gid] = rp;
        g_cursor[gid] = rp;
    }
}

__global__ void k_scatter(const int* __restrict__ src, const int* __restrict__ dst, int E) {
    int e = blockIdx.x * blockDim.x + threadIdx.x;
    if (e < E) {
        int d = dst[e];
        int p = atomicAdd(&g_cursor[d], 1);
        g_col[p] = src[e];
    }
}

// ---------------------------------------------------------------------------
// SGEMM: Y[n,128] = X[n,128] @ W[128,128]^T
// ---------------------------------------------------------------------------
__global__ __launch_bounds__(256) void k_gemm(const float* __restrict__ X,
                                              const float* __restrict__ W,
                                              float* __restrict__ Y, int n) {
    __shared__ float xs[128][17];
    __shared__ float Ws[16][129];

    const int tid  = threadIdx.x;
    const int tcol = tid & 15;
    const int trow = tid >> 4;
    const int br   = blockIdx.x * 128;

    float acc[8][8];
#pragma unroll
    for (int i = 0; i < 8; i++)
#pragma unroll
        for (int j = 0; j < 8; j++) acc[i][j] = 0.0f;

    for (int kt = 0; kt < 128; kt += 16) {
#pragma unroll
        for (int i = 0; i < 8; i++) {
            int idx = tid + i * 256;
            int k = idx & 15, r = idx >> 4;
            int row = br + r;
            xs[r][k] = (row < n) ? X[(size_t)row * 128 + kt + k] : 0.0f;
        }
#pragma unroll
        for (int i = 0; i < 8; i++) {
            int idx = tid + i * 256;
            int k = idx & 15, j = idx >> 4;
            Ws[k][j] = W[(size_t)j * 128 + kt + k];
        }
        __syncthreads();

#pragma unroll
        for (int k = 0; k < 16; k++) {
            float a[8], b[8];
#pragma unroll
            for (int i = 0; i < 8; i++) a[i] = xs[trow + 16 * i][k];
#pragma unroll
            for (int j = 0; j < 8; j++) b[j] = Ws[k][tcol + 16 * j];
#pragma unroll
            for (int i = 0; i < 8; i++)
#pragma unroll
                for (int j = 0; j < 8; j++) acc[i][j] += a[i] * b[j];
        }
        __syncthreads();
    }

#pragma unroll
    for (int i = 0; i < 8; i++) {
        int row = br + trow + 16 * i;
        if (row < n) {
#pragma unroll
            for (int j = 0; j < 8; j++)
                Y[(size_t)row * 128 + tcol + 16 * j] = acc[i][j];
        }
    }
}

// ---------------------------------------------------------------------------
// Gather aggregation (fused with self-loop + bias + perturb):
//   O[d,:] = dinv[d] * ( dinv[d]*H[d,:] + sum_{s in N(d)} dinv[s]*H[s,:] )
//            + bias + P[d,:]
// One warp per dst node; each lane owns 4 contiguous columns (float4).
// ---------------------------------------------------------------------------
__global__ __launch_bounds__(256) void k_gather(const float4* __restrict__ H,
                                                const float* __restrict__ bias,
                                                const float4* __restrict__ P,
                                                float4* __restrict__ O, int n) {
    int warp = (blockIdx.x * blockDim.x + threadIdx.x) >> 5;
    if (warp >= n) return;
    const int lane = threadIdx.x & 31;
    const int d = warp;

    const float dd = g_dinv[d];
    float4 h = H[(size_t)d * 32 + lane];
    float4 acc;
    acc.x = dd * h.x; acc.y = dd * h.y; acc.z = dd * h.z; acc.w = dd * h.w;

    const int start = g_rowptr[d];
    const int cnt   = g_cnt[d];
    int k = 0;
    // 2-wide software pipeline for load-level parallelism
    for (; k + 2 <= cnt; k += 2) {
        int s0 = __ldg(&g_col[start + k]);
        int s1 = __ldg(&g_col[start + k + 1]);
        float w0 = g_dinv[s0];
        float w1 = g_dinv[s1];
        float4 v0 = H[(size_t)s0 * 32 + lane];
        float4 v1 = H[(size_t)s1 * 32 + lane];
        acc.x += w0 * v0.x + w1 * v1.x;
        acc.y += w0 * v0.y + w1 * v1.y;
        acc.z += w0 * v0.z + w1 * v1.z;
        acc.w += w0 * v0.w + w1 * v1.w;
    }
    if (k < cnt) {
        int s0 = __ldg(&g_col[start + k]);
        float w0 = g_dinv[s0];
        float4 v0 = H[(size_t)s0 * 32 + lane];
        acc.x += w0 * v0.x;
        acc.y += w0 * v0.y;
        acc.z += w0 * v0.z;
        acc.w += w0 * v0.w;
    }

    float4 b4 = ((const float4*)bias)[lane];
    float4 p  = P[(size_t)d * 32 + lane];
    float4 o;
    o.x = dd * acc.x + b4.x + p.x;
    o.y = dd * acc.y + b4.y + p.y;
    o.z = dd * acc.z + b4.z + p.z;
    o.w = dd * acc.w + b4.w + p.w;
    O[(size_t)d * 32 + lane] = o;
}

// ---------------------------------------------------------------------------
// Launch
// ---------------------------------------------------------------------------
extern "C" void kernel_launch(void* const* d_in, const int* in_sizes, int n_in,
                              void* d_out, int out_size) {
    const float* x  = (const float*)d_in[0];
    const int*   ei = (const int*)  d_in[1];
    const float* pf = (const float*)d_in[2];
    const float* pl = (const float*)d_in[3];
    const float* W1 = (const float*)d_in[4];
    const float* b1 = (const float*)d_in[5];
    const float* W2 = (const float*)d_in[6];
    const float* b2 = (const float*)d_in[7];
    float* out = (float*)d_out;

    const int n = in_sizes[0] / DD;
    const int E = in_sizes[1] / 2;
    const int* src = ei;
    const int* dst = ei + E;

    float* ph; float* pa;
    cudaGetSymbolAddress((void**)&ph, g_h);
    cudaGetSymbolAddress((void**)&pa, g_a);

    const int T = 256;
    const int nb1024 = (n + 1023) / 1024;

    // CSR build (by destination) + dinv
    k_zero_cnt<<<(n + T - 1) / T, T>>>(n);
    k_count<<<(E + T - 1) / T, T>>>(dst, E);
    k_dinv<<<(n + T - 1) / T, T>>>(n);
    k_scan1<<<nb1024, 1024>>>(n);
    k_scan2<<<1, 1024>>>(nb1024);
    k_scan3<<<nb1024, 1024>>>(n);
    k_scatter<<<(E + T - 1) / T, T>>>(src, dst, E);

    const int gemm_blocks   = (n + 127) / 128;
    const int gather_blocks = (n + 7) / 8;   // 8 warps/block, 1 warp/node

    // Layer 1
    k_gemm<<<gemm_blocks, T>>>(x, W1, ph, n);
    k_gather<<<gather_blocks, T>>>((const float4*)ph, b1, (const float4*)pf, (float4*)pa, n);

    // Layer 2
    k_gemm<<<gemm_blocks, T>>>(pa, W2, ph, n);
    k_gather<<<gather_blocks, T>>>((const float4*)ph, b2, (const float4*)pl, (float4*)out, n);
}

// round 4
// speedup vs baseline: 3.5323x; 1.1923x over previous
#include <cuda_runtime.h>

#define NMAX 100064
#define EMAX 1600000
#define DD   128

// Scratch (allocation-free)
__device__ float g_dinv[NMAX];
__device__ int   g_cnt[NMAX];
__device__ int   g_rowptr[NMAX];
__device__ int   g_cursor[NMAX];
__device__ int   g_col[EMAX];
__device__ int   g_part[1024];
__device__ float g_h[(size_t)NMAX * DD];
__device__ float g_a[(size_t)NMAX * DD];
__device__ float g_wth[DD * DD];   // W transposed, tf32-hi
__device__ float g_wtl[DD * DD];   // W transposed, tf32-lo residual

// ---------------------------------------------------------------------------
// Degree / CSR build
// ---------------------------------------------------------------------------
__global__ void k_zero_cnt(int n) {
    int i = blockIdx.x * blockDim.x + threadIdx.x;
    if (i < n) g_cnt[i] = 0;
}

__global__ void k_count(const int* __restrict__ dst, int E) {
    int e = blockIdx.x * blockDim.x + threadIdx.x;
    if (e < E) atomicAdd(&g_cnt[dst[e]], 1);
}

__global__ void k_dinv(int n) {
    int i = blockIdx.x * blockDim.x + threadIdx.x;
    if (i < n) g_dinv[i] = rsqrtf((float)(g_cnt[i] + 1));
}

__global__ __launch_bounds__(1024) void k_scan1(int n) {
    const int tid = threadIdx.x;
    const int gid = blockIdx.x * 1024 + tid;
    const int lane = tid & 31, wid = tid >> 5;
    int v = (gid < n) ? g_cnt[gid] : 0;
    int x = v;
#pragma unroll
    for (int o = 1; o < 32; o <<= 1) {
        int y = __shfl_up_sync(0xffffffffu, x, o);
        if (lane >= o) x += y;
    }
    __shared__ int wsum[32];
    if (lane == 31) wsum[wid] = x;
    __syncthreads();
    if (wid == 0) {
        int s = wsum[lane];
#pragma unroll
        for (int o = 1; o < 32; o <<= 1) {
            int y = __shfl_up_sync(0xffffffffu, s, o);
            if (lane >= o) s += y;
        }
        wsum[lane] = s;
    }
    __syncthreads();
    int incl = x + (wid > 0 ? wsum[wid - 1] : 0);
    if (gid < n) g_rowptr[gid] = incl - v;
    if (tid == 1023) g_part[blockIdx.x] = incl;
}

__global__ __launch_bounds__(1024) void k_scan2(int nb) {
    const int tid = threadIdx.x;
    const int lane = tid & 31, wid = tid >> 5;
    int v = (tid < nb) ? g_part[tid] : 0;
    int x = v;
#pragma unroll
    for (int o = 1; o < 32; o <<= 1) {
        int y = __shfl_up_sync(0xffffffffu, x, o);
        if (lane >= o) x += y;
    }
    __shared__ int wsum[32];
    if (lane == 31) wsum[wid] = x;
    __syncthreads();
    if (wid == 0) {
        int s = wsum[lane];
#pragma unroll
        for (int o = 1; o < 32; o <<= 1) {
            int y = __shfl_up_sync(0xffffffffu, s, o);
            if (lane >= o) s += y;
        }
        wsum[lane] = s;
    }
    __syncthreads();
    int excl = x - v + (wid > 0 ? wsum[wid - 1] : 0);
    if (tid < nb) g_part[tid] = excl;
}

__global__ __launch_bounds__(1024) void k_scan3(int n) {
    int gid = blockIdx.x * 1024 + threadIdx.x;
    if (gid < n) {
        int rp = g_rowptr[gid] + g_part[blockIdx.x];
        g_rowptr[gid] = rp;
        g_cursor[gid] = rp;
    }
}

__global__ void k_scatter(const int* __restrict__ src, const int* __restrict__ dst, int E) {
    int e = blockIdx.x * blockDim.x + threadIdx.x;
    if (e < E) {
        int d = dst[e];
        int p = atomicAdd(&g_cursor[d], 1);
        g_col[p] = src[e];
    }
}

// ---------------------------------------------------------------------------
// Split W into tf32 hi/lo and transpose: Wt*[k][j] = split(W[j][k])
// ---------------------------------------------------------------------------
__global__ void k_split_w(const float* __restrict__ W) {
    int i = blockIdx.x * blockDim.x + threadIdx.x;
    if (i >= DD * DD) return;
    int j = i >> 7, k = i & 127;
    float v = W[j * DD + k];
    unsigned h;
    asm("cvt.rna.tf32.f32 %0, %1;" : "=r"(h) : "f"(v));
    float resid = v - __uint_as_float(h);
    unsigned l;
    asm("cvt.rna.tf32.f32 %0, %1;" : "=r"(l) : "f"(resid));
    g_wth[k * DD + j] = __uint_as_float(h);
    g_wtl[k * DD + j] = __uint_as_float(l);
}

// ---------------------------------------------------------------------------
// Tensor-core GEMM (3xTF32): Y[n,128] = X[n,128] @ W^T
// Block: 128 rows x 128 cols, 8 warps; warp = 16 rows x 128 cols
// mma.sync.m16n8k8 tf32, fp32 accum. 3 terms: hi*hi + lo*hi + hi*lo.
// ---------------------------------------------------------------------------
#define MMA_TF32(C, A, B0, B1)                                                 \
    asm volatile("mma.sync.aligned.m16n8k8.row.col.f32.tf32.tf32.f32 "        \
                 "{%0,%1,%2,%3}, {%4,%5,%6,%7}, {%8,%9}, {%0,%1,%2,%3};"      \
                 : "+f"(C[0]), "+f"(C[1]), "+f"(C[2]), "+f"(C[3])             \
                 : "r"(A[0]), "r"(A[1]), "r"(A[2]), "r"(A[3]), "r"(B0), "r"(B1))

__global__ __launch_bounds__(256) void k_gemm_tc(const float* __restrict__ X,
                                                 float* __restrict__ Y, int n) {
    __shared__ float xs[128][36];    // [row][k] pad->conflict-free frag loads
    __shared__ float wh[32][136];    // [k][j] hi, pad 136 -> banks tig*8+g
    __shared__ float wl[32][136];    // [k][j] lo

    const int tid  = threadIdx.x;
    const int warp = tid >> 5;
    const int lane = tid & 31;
    const int g    = lane >> 2;   // groupID 0..7
    const int tig  = lane & 3;    // 0..3
    const int br   = blockIdx.x * 128;
    const int rb   = warp * 16;

    float c[16][4];
#pragma unroll
    for (int nt = 0; nt < 16; nt++)
#pragma unroll
        for (int q = 0; q < 4; q++) c[nt][q] = 0.0f;

    for (int kc = 0; kc < 128; kc += 32) {
        // X tile: 128x32 floats = 1024 float4
#pragma unroll
        for (int j = 0; j < 4; j++) {
            int i = tid + j * 256;
            int r = i >> 3, kq = (i & 7) * 4;
            float4 v = make_float4(0.f, 0.f, 0.f, 0.f);
            if (br + r < n) v = *(const float4*)&X[(size_t)(br + r) * 128 + kc + kq];
            *(float4*)&xs[r][kq] = v;
        }
        // W tiles: 32x128 floats each = 1024 float4 each
#pragma unroll
        for (int j = 0; j < 4; j++) {
            int i = tid + j * 256;
            int k = i >> 5, jq = (i & 31) * 4;
            *(float4*)&wh[k][jq] = *(const float4*)&g_wth[(kc + k) * 128 + jq];
            *(float4*)&wl[k][jq] = *(const float4*)&g_wtl[(kc + k) * 128 + jq];
        }
        __syncthreads();

#pragma unroll
        for (int ks = 0; ks < 32; ks += 8) {
            float a_raw[4];
            a_raw[0] = xs[rb + g][ks + tig];
            a_raw[1] = xs[rb + g + 8][ks + tig];
            a_raw[2] = xs[rb + g][ks + tig + 4];
            a_raw[3] = xs[rb + g + 8][ks + tig + 4];
            unsigned ah[4], al[4];
#pragma unroll
            for (int q = 0; q < 4; q++) {
                asm("cvt.rna.tf32.f32 %0, %1;" : "=r"(ah[q]) : "f"(a_raw[q]));
                float resid = a_raw[q] - __uint_as_float(ah[q]);
                asm("cvt.rna.tf32.f32 %0, %1;" : "=r"(al[q]) : "f"(resid));
            }
#pragma unroll
            for (int nt = 0; nt < 16; nt++) {
                int col = nt * 8 + g;
                unsigned bh0 = __float_as_uint(wh[ks + tig][col]);
                unsigned bh1 = __float_as_uint(wh[ks + tig + 4][col]);
                unsigned bl0 = __float_as_uint(wl[ks + tig][col]);
                unsigned bl1 = __float_as_uint(wl[ks + tig + 4][col]);
                MMA_TF32(c[nt], ah, bh0, bh1);   // hi*hi
                MMA_TF32(c[nt], al, bh0, bh1);   // lo*hi
                MMA_TF32(c[nt], ah, bl0, bl1);   // hi*lo
            }
        }
        __syncthreads();
    }

    // Epilogue: c0,c1 -> (row g, cols 2tig,2tig+1); c2,c3 -> row g+8
    const int row0 = br + rb + g;
    const int row1 = row0 + 8;
#pragma unroll
    for (int nt = 0; nt < 16; nt++) {
        int col = nt * 8 + tig * 2;
        if (row0 < n) *(float2*)&Y[(size_t)row0 * 128 + col] = make_float2(c[nt][0], c[nt][1]);
        if (row1 < n) *(float2*)&Y[(size_t)row1 * 128 + col] = make_float2(c[nt][2], c[nt][3]);
    }
}

// ---------------------------------------------------------------------------
// Gather aggregation (fused self-loop + bias + perturb)
// ---------------------------------------------------------------------------
__global__ __launch_bounds__(256) void k_gather(const float4* __restrict__ H,
                                                const float* __restrict__ bias,
                                                const float4* __restrict__ P,
                                                float4* __restrict__ O, int n) {
    int warp = (blockIdx.x * blockDim.x + threadIdx.x) >> 5;
    if (warp >= n) return;
    const int lane = threadIdx.x & 31;
    const int d = warp;

    const float dd = g_dinv[d];
    float4 h = H[(size_t)d * 32 + lane];
    float4 acc;
    acc.x = dd * h.x; acc.y = dd * h.y; acc.z = dd * h.z; acc.w = dd * h.w;

    const int start = g_rowptr[d];
    const int cnt   = g_cnt[d];
    int k = 0;
    for (; k + 2 <= cnt; k += 2) {
        int s0 = __ldg(&g_col[start + k]);
        int s1 = __ldg(&g_col[start + k + 1]);
        float w0 = g_dinv[s0];
        float w1 = g_dinv[s1];
        float4 v0 = H[(size_t)s0 * 32 + lane];
        float4 v1 = H[(size_t)s1 * 32 + lane];
        acc.x += w0 * v0.x + w1 * v1.x;
        acc.y += w0 * v0.y + w1 * v1.y;
        acc.z += w0 * v0.z + w1 * v1.z;
        acc.w += w0 * v0.w + w1 * v1.w;
    }
    if (k < cnt) {
        int s0 = __ldg(&g_col[start + k]);
        float w0 = g_dinv[s0];
        float4 v0 = H[(size_t)s0 * 32 + lane];
        acc.x += w0 * v0.x;
        acc.y += w0 * v0.y;
        acc.z += w0 * v0.z;
        acc.w += w0 * v0.w;
    }

    float4 b4 = ((const float4*)bias)[lane];
    float4 p  = P[(size_t)d * 32 + lane];
    float4 o;
    o.x = dd * acc.x + b4.x + p.x;
    o.y = dd * acc.y + b4.y + p.y;
    o.z = dd * acc.z + b4.z + p.z;
    o.w = dd * acc.w + b4.w + p.w;
    O[(size_t)d * 32 + lane] = o;
}

// ---------------------------------------------------------------------------
// Launch
// ---------------------------------------------------------------------------
extern "C" void kernel_launch(void* const* d_in, const int* in_sizes, int n_in,
                              void* d_out, int out_size) {
    const float* x  = (const float*)d_in[0];
    const int*   ei = (const int*)  d_in[1];
    const float* pf = (const float*)d_in[2];
    const float* pl = (const float*)d_in[3];
    const float* W1 = (const float*)d_in[4];
    const float* b1 = (const float*)d_in[5];
    const float* W2 = (const float*)d_in[6];
    const float* b2 = (const float*)d_in[7];
    float* out = (float*)d_out;

    const int n = in_sizes[0] / DD;
    const int E = in_sizes[1] / 2;
    const int* src = ei;
    const int* dst = ei + E;

    float* ph; float* pa;
    cudaGetSymbolAddress((void**)&ph, g_h);
    cudaGetSymbolAddress((void**)&pa, g_a);

    const int T = 256;
    const int nb1024 = (n + 1023) / 1024;

    // CSR build + dinv
    k_zero_cnt<<<(n + T - 1) / T, T>>>(n);
    k_count<<<(E + T - 1) / T, T>>>(dst, E);
    k_dinv<<<(n + T - 1) / T, T>>>(n);
    k_scan1<<<nb1024, 1024>>>(n);
    k_scan2<<<1, 1024>>>(nb1024);
    k_scan3<<<nb1024, 1024>>>(n);
    k_scatter<<<(E + T - 1) / T, T>>>(src, dst, E);

    const int gemm_blocks   = (n + 127) / 128;
    const int gather_blocks = (n + 7) / 8;
    const int splitw_blocks = (DD * DD + T - 1) / T;

    // Layer 1
    k_split_w<<<splitw_blocks, T>>>(W1);
    k_gemm_tc<<<gemm_blocks, T>>>(x, ph, n);
    k_gather<<<gather_blocks, T>>>((const float4*)ph, b1, (const float4*)pf, (float4*)pa, n);

    // Layer 2
    k_split_w<<<splitw_blocks, T>>>(W2);
    k_gemm_tc<<<gemm_blocks, T>>>(pa, ph, n);
    k_gather<<<gather_blocks, T>>>((const float4*)ph, b2, (const float4*)pl, (float4*)out, n);
}

// round 6
// speedup vs baseline: 3.7546x; 1.0629x over previous
#include <cuda_runtime.h>

#define NMAX 100064
#define EMAX 1600000
#define DD   128

// Scratch (allocation-free)
__device__ float g_dinv[NMAX];
__device__ int   g_cnt[NMAX];
__device__ int   g_rowptr[NMAX];
__device__ int   g_cursor[NMAX];
__device__ int   g_col[EMAX];
__device__ int   g_part[1024];
__device__ float g_h[(size_t)NMAX * DD];
__device__ float g_a[(size_t)NMAX * DD];
__device__ float g_w1h[DD * DD];
__device__ float g_w1l[DD * DD];
__device__ float g_w2h[DD * DD];
__device__ float g_w2l[DD * DD];

// ---------------------------------------------------------------------------
// Degree / CSR build
// ---------------------------------------------------------------------------
__global__ void k_zero_cnt(int n) {
    int i = blockIdx.x * blockDim.x + threadIdx.x;
    if (i < n) g_cnt[i] = 0;
}

__global__ void k_count(const int* __restrict__ dst, int E) {
    int e = blockIdx.x * blockDim.x + threadIdx.x;
    if (e < E) atomicAdd(&g_cnt[dst[e]], 1);
}

// Scan level-1 + fused dinv computation.
__global__ __launch_bounds__(1024) void k_scan1(int n) {
    const int tid = threadIdx.x;
    const int gid = blockIdx.x * 1024 + tid;
    const int lane = tid & 31, wid = tid >> 5;
    int v = (gid < n) ? g_cnt[gid] : 0;
    if (gid < n) g_dinv[gid] = rsqrtf((float)(v + 1));  // fused dinv (+self loop)
    int x = v;
#pragma unroll
    for (int o = 1; o < 32; o <<= 1) {
        int y = __shfl_up_sync(0xffffffffu, x, o);
        if (lane >= o) x += y;
    }
    __shared__ int wsum[32];
    if (lane == 31) wsum[wid] = x;
    __syncthreads();
    if (wid == 0) {
        int s = wsum[lane];
#pragma unroll
        for (int o = 1; o < 32; o <<= 1) {
            int y = __shfl_up_sync(0xffffffffu, s, o);
            if (lane >= o) s += y;
        }
        wsum[lane] = s;
    }
    __syncthreads();
    int incl = x + (wid > 0 ? wsum[wid - 1] : 0);
    if (gid < n) g_rowptr[gid] = incl - v;
    if (tid == 1023) g_part[blockIdx.x] = incl;
}

__global__ __launch_bounds__(1024) void k_scan2(int nb) {
    const int tid = threadIdx.x;
    const int lane = tid & 31, wid = tid >> 5;
    int v = (tid < nb) ? g_part[tid] : 0;
    int x = v;
#pragma unroll
    for (int o = 1; o < 32; o <<= 1) {
        int y = __shfl_up_sync(0xffffffffu, x, o);
        if (lane >= o) x += y;
    }
    __shared__ int wsum[32];
    if (lane == 31) wsum[wid] = x;
    __syncthreads();
    if (wid == 0) {
        int s = wsum[lane];
#pragma unroll
        for (int o = 1; o < 32; o <<= 1) {
            int y = __shfl_up_sync(0xffffffffu, s, o);
            if (lane >= o) s += y;
        }
        wsum[lane] = s;
    }
    __syncthreads();
    int excl = x - v + (wid > 0 ? wsum[wid - 1] : 0);
    if (tid < nb) g_part[tid] = excl;
}

__global__ __launch_bounds__(1024) void k_scan3(int n) {
    int gid = blockIdx.x * 1024 + threadIdx.x;
    if (gid < n) {
        int rp = g_rowptr[gid] + g_part[blockIdx.x];
        g_rowptr[gid] = rp;
        g_cursor[gid] = rp;
    }
}

__global__ void k_scatter(const int* __restrict__ src, const int* __restrict__ dst, int E) {
    int e = blockIdx.x * blockDim.x + threadIdx.x;
    if (e < E) {
        int d = dst[e];
        int p = atomicAdd(&g_cursor[d], 1);
        g_col[p] = src[e];
    }
}

// ---------------------------------------------------------------------------
// Split W into tf32 hi/lo and transpose: Wt*[k][j] = split(W[j][k])
// ---------------------------------------------------------------------------
__global__ void k_split_w(const float* __restrict__ W,
                          float* __restrict__ Wh, float* __restrict__ Wl) {
    int i = blockIdx.x * blockDim.x + threadIdx.x;
    if (i >= DD * DD) return;
    int j = i >> 7, k = i & 127;
    float v = W[j * DD + k];
    unsigned h;
    asm("cvt.rna.tf32.f32 %0, %1;" : "=r"(h) : "f"(v));
    float resid = v - __uint_as_float(h);
    unsigned l;
    asm("cvt.rna.tf32.f32 %0, %1;" : "=r"(l) : "f"(resid));
    Wh[k * DD + j] = __uint_as_float(h);
    Wl[k * DD + j] = __uint_as_float(l);
}

// ---------------------------------------------------------------------------
// Tensor-core GEMM (3xTF32): Y[n,128] = X[n,128] @ W^T
// ---------------------------------------------------------------------------
#define MMA_TF32(C, A, B0, B1)                                                 \
    asm volatile("mma.sync.aligned.m16n8k8.row.col.f32.tf32.tf32.f32 "        \
                 "{%0,%1,%2,%3}, {%4,%5,%6,%7}, {%8,%9}, {%0,%1,%2,%3};"      \
                 : "+f"(C[0]), "+f"(C[1]), "+f"(C[2]), "+f"(C[3])             \
                 : "r"(A[0]), "r"(A[1]), "r"(A[2]), "r"(A[3]), "r"(B0), "r"(B1))

__global__ __launch_bounds__(256) void k_gemm_tc(const float* __restrict__ X,
                                                 const float* __restrict__ Wth,
                                                 const float* __restrict__ Wtl,
                                                 float* __restrict__ Y, int n) {
    __shared__ float xs[128][36];
    __shared__ float wh[32][136];
    __shared__ float wl[32][136];

    const int tid  = threadIdx.x;
    const int warp = tid >> 5;
    const int lane = tid & 31;
    const int g    = lane >> 2;
    const int tig  = lane & 3;
    const int br   = blockIdx.x * 128;
    const int rb   = warp * 16;

    float c[16][4];
#pragma unroll
    for (int nt = 0; nt < 16; nt++)
#pragma unroll
        for (int q = 0; q < 4; q++) c[nt][q] = 0.0f;

    for (int kc = 0; kc < 128; kc += 32) {
#pragma unroll
        for (int j = 0; j < 4; j++) {
            int i = tid + j * 256;
            int r = i >> 3, kq = (i & 7) * 4;
            float4 v = make_float4(0.f, 0.f, 0.f, 0.f);
            if (br + r < n) v = *(const float4*)&X[(size_t)(br + r) * 128 + kc + kq];
            *(float4*)&xs[r][kq] = v;
        }
#pragma unroll
        for (int j = 0; j < 4; j++) {
            int i = tid + j * 256;
            int k = i >> 5, jq = (i & 31) * 4;
            *(float4*)&wh[k][jq] = *(const float4*)&Wth[(kc + k) * 128 + jq];
            *(float4*)&wl[k][jq] = *(const float4*)&Wtl[(kc + k) * 128 + jq];
        }
        __syncthreads();

#pragma unroll
        for (int ks = 0; ks < 32; ks += 8) {
            float a_raw[4];
            a_raw[0] = xs[rb + g][ks + tig];
            a_raw[1] = xs[rb + g + 8][ks + tig];
            a_raw[2] = xs[rb + g][ks + tig + 4];
            a_raw[3] = xs[rb + g + 8][ks + tig + 4];
            unsigned ah[4], al[4];
#pragma unroll
            for (int q = 0; q < 4; q++) {
                asm("cvt.rna.tf32.f32 %0, %1;" : "=r"(ah[q]) : "f"(a_raw[q]));
                float resid = a_raw[q] - __uint_as_float(ah[q]);
                asm("cvt.rna.tf32.f32 %0, %1;" : "=r"(al[q]) : "f"(resid));
            }
#pragma unroll
            for (int nt = 0; nt < 16; nt++) {
                int col = nt * 8 + g;
                unsigned bh0 = __float_as_uint(wh[ks + tig][col]);
                unsigned bh1 = __float_as_uint(wh[ks + tig + 4][col]);
                unsigned bl0 = __float_as_uint(wl[ks + tig][col]);
                unsigned bl1 = __float_as_uint(wl[ks + tig + 4][col]);
                MMA_TF32(c[nt], ah, bh0, bh1);
                MMA_TF32(c[nt], al, bh0, bh1);
                MMA_TF32(c[nt], ah, bl0, bl1);
            }
        }
        __syncthreads();
    }

    const int row0 = br + rb + g;
    const int row1 = row0 + 8;
#pragma unroll
    for (int nt = 0; nt < 16; nt++) {
        int col = nt * 8 + tig * 2;
        if (row0 < n) *(float2*)&Y[(size_t)row0 * 128 + col] = make_float2(c[nt][0], c[nt][1]);
        if (row1 < n) *(float2*)&Y[(size_t)row1 * 128 + col] = make_float2(c[nt][2], c[nt][3]);
    }
}

// ---------------------------------------------------------------------------
// Gather aggregation (fused self-loop + bias + perturb), 4-wide pipeline
// ---------------------------------------------------------------------------
__global__ __launch_bounds__(256) void k_gather(const float4* __restrict__ H,
                                                const float* __restrict__ bias,
                                                const float4* __restrict__ P,
                                                float4* __restrict__ O, int n) {
    int warp = (blockIdx.x * blockDim.x + threadIdx.x) >> 5;
    if (warp >= n) return;
    const int lane = threadIdx.x & 31;
    const int d = warp;

    const float dd = g_dinv[d];
    float4 h = H[(size_t)d * 32 + lane];
    float4 acc;
    acc.x = dd * h.x; acc.y = dd * h.y; acc.z = dd * h.z; acc.w = dd * h.w;

    const int start = g_rowptr[d];
    const int cnt   = g_cnt[d];
    int k = 0;
    for (; k + 4 <= cnt; k += 4) {
        int s0 = __ldg(&g_col[start + k]);
        int s1 = __ldg(&g_col[start + k + 1]);
        int s2 = __ldg(&g_col[start + k + 2]);
        int s3 = __ldg(&g_col[start + k + 3]);
        float w0 = g_dinv[s0], w1 = g_dinv[s1], w2 = g_dinv[s2], w3 = g_dinv[s3];
        float4 v0 = H[(size_t)s0 * 32 + lane];
        float4 v1 = H[(size_t)s1 * 32 + lane];
        float4 v2 = H[(size_t)s2 * 32 + lane];
        float4 v3 = H[(size_t)s3 * 32 + lane];
        acc.x += w0 * v0.x + w1 * v1.x + w2 * v2.x + w3 * v3.x;
        acc.y += w0 * v0.y + w1 * v1.y + w2 * v2.y + w3 * v3.y;
        acc.z += w0 * v0.z + w1 * v1.z + w2 * v2.z + w3 * v3.z;
        acc.w += w0 * v0.w + w1 * v1.w + w2 * v2.w + w3 * v3.w;
    }
    for (; k < cnt; k++) {
        int s0 = __ldg(&g_col[start + k]);
        float w0 = g_dinv[s0];
        float4 v0 = H[(size_t)s0 * 32 + lane];
        acc.x += w0 * v0.x;
        acc.y += w0 * v0.y;
        acc.z += w0 * v0.z;
        acc.w += w0 * v0.w;
    }

    float4 b4 = ((const float4*)bias)[lane];
    float4 p  = P[(size_t)d * 32 + lane];
    float4 o;
    o.x = dd * acc.x + b4.x + p.x;
    o.y = dd * acc.y + b4.y + p.y;
    o.z = dd * acc.z + b4.z + p.z;
    o.w = dd * acc.w + b4.w + p.w;
    O[(size_t)d * 32 + lane] = o;
}

// ---------------------------------------------------------------------------
// Launch: CSR build (main stream) overlapped with W-split + GEMM1 (side stream)
// ---------------------------------------------------------------------------
extern "C" void kernel_launch(void* const* d_in, const int* in_sizes, int n_in,
                              void* d_out, int out_size) {
    const float* x  = (const float*)d_in[0];
    const int*   ei = (const int*)  d_in[1];
    const float* pf = (const float*)d_in[2];
    const float* pl = (const float*)d_in[3];
    const float* W1 = (const float*)d_in[4];
    const float* b1 = (const float*)d_in[5];
    const float* W2 = (const float*)d_in[6];
    const float* b2 = (const float*)d_in[7];
    float* out = (float*)d_out;

    const int n = in_sizes[0] / DD;
    const int E = in_sizes[1] / 2;
    const int* src = ei;
    const int* dst = ei + E;

    float* ph; float* pa;
    float* w1h; float* w1l; float* w2h; float* w2l;
    cudaGetSymbolAddress((void**)&ph, g_h);
    cudaGetSymbolAddress((void**)&pa, g_a);
    cudaGetSymbolAddress((void**)&w1h, g_w1h);
    cudaGetSymbolAddress((void**)&w1l, g_w1l);
    cudaGetSymbolAddress((void**)&w2h, g_w2h);
    cudaGetSymbolAddress((void**)&w2l, g_w2l);

    // One-time stream/event setup (first call is the uncaptured correctness run).
    static cudaStream_t s2 = nullptr;
    static cudaEvent_t evFork = nullptr, evJoin = nullptr;
    if (!s2) {
        cudaStreamCreateWithFlags(&s2, cudaStreamNonBlocking);
        cudaEventCreateWithFlags(&evFork, cudaEventDisableTiming);
        cudaEventCreateWithFlags(&evJoin, cudaEventDisableTiming);
    }

    const int T = 256;
    const int nb1024 = (n + 1023) / 1024;
    const int gemm_blocks   = (n + 127) / 128;
    const int gather_blocks = (n + 7) / 8;
    const int splitw_blocks = (DD * DD + T - 1) / T;

    // Fork: side stream does W splits + GEMM1 while main stream builds CSR.
    cudaEventRecord(evFork, 0);
    cudaStreamWaitEvent(s2, evFork, 0);

    k_split_w<<<splitw_blocks, T, 0, s2>>>(W1, w1h, w1l);
    k_split_w<<<splitw_blocks, T, 0, s2>>>(W2, w2h, w2l);
    k_gemm_tc<<<gemm_blocks, T, 0, s2>>>(x, w1h, w1l, ph, n);
    cudaEventRecord(evJoin, s2);

    // Main stream: CSR build + dinv
    k_zero_cnt<<<(n + T - 1) / T, T>>>(n);
    k_count<<<(E + T - 1) / T, T>>>(dst, E);
    k_scan1<<<nb1024, 1024>>>(n);     // also computes dinv
    k_scan2<<<1, 1024>>>(nb1024);
    k_scan3<<<nb1024, 1024>>>(n);
    k_scatter<<<(E + T - 1) / T, T>>>(src, dst, E);

    // Join: gather1 needs both CSR and GEMM1.
    cudaStreamWaitEvent(0, evJoin, 0);

    k_gather<<<gather_blocks, T>>>((const float4*)ph, b1, (const float4*)pf, (float4*)pa, n);
    k_gemm_tc<<<gemm_blocks, T>>>(pa, w2h, w2l, ph, n);
    k_gather<<<gather_blocks, T>>>((const float4*)ph, b2, (const float4*)pl, (float4*)out, n);
}

// round 8
// speedup vs baseline: 3.8396x; 1.0226x over previous
#include <cuda_runtime.h>
#include <cuda_fp16.h>

#define NMAX 100064
#define EMAX 1600000
#define DD   128

// Scratch (allocation-free)
__device__ float g_dinv[NMAX];
__device__ int   g_cnt[NMAX];
__device__ int   g_rowptr[NMAX];
__device__ int   g_cursor[NMAX];
__device__ int   g_col[EMAX];
__device__ int   g_part[1024];
__device__ __half g_h[(size_t)NMAX * DD];   // GEMM output in fp16 (gather payload)
__device__ float  g_a[(size_t)NMAX * DD];   // layer-1 aggregated output (fp32)
__device__ float g_w1h[DD * DD];
__device__ float g_w1l[DD * DD];
__device__ float g_w2h[DD * DD];
__device__ float g_w2l[DD * DD];

// ---------------------------------------------------------------------------
// Degree / CSR build
// ---------------------------------------------------------------------------
__global__ void k_zero_cnt(int n) {
    int i = blockIdx.x * blockDim.x + threadIdx.x;
    if (i < n) g_cnt[i] = 0;
}

__global__ void k_count(const int* __restrict__ dst, int E) {
    int e = blockIdx.x * blockDim.x + threadIdx.x;
    if (e < E) atomicAdd(&g_cnt[dst[e]], 1);
}

__global__ __launch_bounds__(1024) void k_scan1(int n) {
    const int tid = threadIdx.x;
    const int gid = blockIdx.x * 1024 + tid;
    const int lane = tid & 31, wid = tid >> 5;
    int v = (gid < n) ? g_cnt[gid] : 0;
    if (gid < n) g_dinv[gid] = rsqrtf((float)(v + 1));
    int x = v;
#pragma unroll
    for (int o = 1; o < 32; o <<= 1) {
        int y = __shfl_up_sync(0xffffffffu, x, o);
        if (lane >= o) x += y;
    }
    __shared__ int wsum[32];
    if (lane == 31) wsum[wid] = x;
    __syncthreads();
    if (wid == 0) {
        int s = wsum[lane];
#pragma unroll
        for (int o = 1; o < 32; o <<= 1) {
            int y = __shfl_up_sync(0xffffffffu, s, o);
            if (lane >= o) s += y;
        }
        wsum[lane] = s;
    }
    __syncthreads();
    int incl = x + (wid > 0 ? wsum[wid - 1] : 0);
    if (gid < n) g_rowptr[gid] = incl - v;
    if (tid == 1023) g_part[blockIdx.x] = incl;
}

__global__ __launch_bounds__(1024) void k_scan2(int nb) {
    const int tid = threadIdx.x;
    const int lane = tid & 31, wid = tid >> 5;
    int v = (tid < nb) ? g_part[tid] : 0;
    int x = v;
#pragma unroll
    for (int o = 1; o < 32; o <<= 1) {
        int y = __shfl_up_sync(0xffffffffu, x, o);
        if (lane >= o) x += y;
    }
    __shared__ int wsum[32];
    if (lane == 31) wsum[wid] = x;
    __syncthreads();
    if (wid == 0) {
        int s = wsum[lane];
#pragma unroll
        for (int o = 1; o < 32; o <<= 1) {
            int y = __shfl_up_sync(0xffffffffu, s, o);
            if (lane >= o) s += y;
        }
        wsum[lane] = s;
    }
    __syncthreads();
    int excl = x - v + (wid > 0 ? wsum[wid - 1] : 0);
    if (tid < nb) g_part[tid] = excl;
}

__global__ __launch_bounds__(1024) void k_scan3(int n) {
    int gid = blockIdx.x * 1024 + threadIdx.x;
    if (gid < n) {
        int rp = g_rowptr[gid] + g_part[blockIdx.x];
        g_rowptr[gid] = rp;
        g_cursor[gid] = rp;
    }
}

__global__ void k_scatter(const int* __restrict__ src, const int* __restrict__ dst, int E) {
    int e = blockIdx.x * blockDim.x + threadIdx.x;
    if (e < E) {
        int d = dst[e];
        int p = atomicAdd(&g_cursor[d], 1);
        g_col[p] = src[e];
    }
}

// ---------------------------------------------------------------------------
// Split W into tf32 hi/lo and transpose
// ---------------------------------------------------------------------------
__global__ void k_split_w(const float* __restrict__ W,
                          float* __restrict__ Wh, float* __restrict__ Wl) {
    int i = blockIdx.x * blockDim.x + threadIdx.x;
    if (i >= DD * DD) return;
    int j = i >> 7, k = i & 127;
    float v = W[j * DD + k];
    unsigned h;
    asm("cvt.rna.tf32.f32 %0, %1;" : "=r"(h) : "f"(v));
    float resid = v - __uint_as_float(h);
    unsigned l;
    asm("cvt.rna.tf32.f32 %0, %1;" : "=r"(l) : "f"(resid));
    Wh[k * DD + j] = __uint_as_float(h);
    Wl[k * DD + j] = __uint_as_float(l);
}

// ---------------------------------------------------------------------------
// Tensor-core GEMM (3xTF32): Y[n,128](fp16) = X[n,128](fp32) @ W^T
// ---------------------------------------------------------------------------
#define MMA_TF32(C, A, B0, B1)                                                 \
    asm volatile("mma.sync.aligned.m16n8k8.row.col.f32.tf32.tf32.f32 "        \
                 "{%0,%1,%2,%3}, {%4,%5,%6,%7}, {%8,%9}, {%0,%1,%2,%3};"      \
                 : "+f"(C[0]), "+f"(C[1]), "+f"(C[2]), "+f"(C[3])             \
                 : "r"(A[0]), "r"(A[1]), "r"(A[2]), "r"(A[3]), "r"(B0), "r"(B1))

__global__ __launch_bounds__(256) void k_gemm_tc(const float* __restrict__ X,
                                                 const float* __restrict__ Wth,
                                                 const float* __restrict__ Wtl,
                                                 __half* __restrict__ Y, int n) {
    __shared__ float xs[128][36];
    __shared__ float wh[32][136];
    __shared__ float wl[32][136];

    const int tid  = threadIdx.x;
    const int warp = tid >> 5;
    const int lane = tid & 31;
    const int g    = lane >> 2;
    const int tig  = lane & 3;
    const int br   = blockIdx.x * 128;
    const int rb   = warp * 16;

    float c[16][4];
#pragma unroll
    for (int nt = 0; nt < 16; nt++)
#pragma unroll
        for (int q = 0; q < 4; q++) c[nt][q] = 0.0f;

    for (int kc = 0; kc < 128; kc += 32) {
#pragma unroll
        for (int j = 0; j < 4; j++) {
            int i = tid + j * 256;
            int r = i >> 3, kq = (i & 7) * 4;
            float4 v = make_float4(0.f, 0.f, 0.f, 0.f);
            if (br + r < n) v = *(const float4*)&X[(size_t)(br + r) * 128 + kc + kq];
            *(float4*)&xs[r][kq] = v;
        }
#pragma unroll
        for (int j = 0; j < 4; j++) {
            int i = tid + j * 256;
            int k = i >> 5, jq = (i & 31) * 4;
            *(float4*)&wh[k][jq] = *(const float4*)&Wth[(kc + k) * 128 + jq];
            *(float4*)&wl[k][jq] = *(const float4*)&Wtl[(kc + k) * 128 + jq];
        }
        __syncthreads();

#pragma unroll
        for (int ks = 0; ks < 32; ks += 8) {
            float a_raw[4];
            a_raw[0] = xs[rb + g][ks + tig];
            a_raw[1] = xs[rb + g + 8][ks + tig];
            a_raw[2] = xs[rb + g][ks + tig + 4];
            a_raw[3] = xs[rb + g + 8][ks + tig + 4];
            unsigned ah[4], al[4];
#pragma unroll
            for (int q = 0; q < 4; q++) {
                asm("cvt.rna.tf32.f32 %0, %1;" : "=r"(ah[q]) : "f"(a_raw[q]));
                float resid = a_raw[q] - __uint_as_float(ah[q]);
                asm("cvt.rna.tf32.f32 %0, %1;" : "=r"(al[q]) : "f"(resid));
            }
#pragma unroll
            for (int nt = 0; nt < 16; nt++) {
                int col = nt * 8 + g;
                unsigned bh0 = __float_as_uint(wh[ks + tig][col]);
                unsigned bh1 = __float_as_uint(wh[ks + tig + 4][col]);
                unsigned bl0 = __float_as_uint(wl[ks + tig][col]);
                unsigned bl1 = __float_as_uint(wl[ks + tig + 4][col]);
                MMA_TF32(c[nt], ah, bh0, bh1);
                MMA_TF32(c[nt], al, bh0, bh1);
                MMA_TF32(c[nt], ah, bl0, bl1);
            }
        }
        __syncthreads();
    }

    const int row0 = br + rb + g;
    const int row1 = row0 + 8;
#pragma unroll
    for (int nt = 0; nt < 16; nt++) {
        int col = nt * 8 + tig * 2;
        if (row0 < n)
            *(__half2*)&Y[(size_t)row0 * 128 + col] = __floats2half2_rn(c[nt][0], c[nt][1]);
        if (row1 < n)
            *(__half2*)&Y[(size_t)row1 * 128 + col] = __floats2half2_rn(c[nt][2], c[nt][3]);
    }
}

// ---------------------------------------------------------------------------
// Gather aggregation (fp16 payload, shuffle-distributed indices):
//   O[d,:] = dinv[d]*(dinv[d]*H[d,:] + sum dinv[s]*H[s,:]) + bias + P[d,:]
// One warp per node; lane owns 4 columns (8B fp16 load per row).
// ---------------------------------------------------------------------------
__device__ __forceinline__ float4 ld_row_h4(const __half* __restrict__ H, int s, int lane) {
    uint2 u = *(const uint2*)(H + (size_t)s * 128 + lane * 4);
    float2 f0 = __half22float2(*(__half2*)&u.x);
    float2 f1 = __half22float2(*(__half2*)&u.y);
    return make_float4(f0.x, f0.y, f1.x, f1.y);
}

__global__ __launch_bounds__(256) void k_gather(const __half* __restrict__ H,
                                                const float* __restrict__ bias,
                                                const float4* __restrict__ P,
                                                float4* __restrict__ O,
                                                int off, int nchunk) {
    int w = (blockIdx.x * blockDim.x + threadIdx.x) >> 5;
    if (w >= nchunk) return;
    const int lane = threadIdx.x & 31;
    const int d = off + w;

    const float dd = g_dinv[d];
    float4 h = ld_row_h4(H, d, lane);
    float4 acc;
    acc.x = dd * h.x; acc.y = dd * h.y; acc.z = dd * h.z; acc.w = dd * h.w;

    const int start = g_rowptr[d];
    const int cnt   = g_cnt[d];

    for (int base = 0; base < cnt; base += 32) {
        int m = cnt - base; if (m > 32) m = 32;
        int idx = 0; float wv = 0.0f;
        if (lane < m) {
            idx = __ldg(&g_col[start + base + lane]);
            wv  = g_dinv[idx];
        }
        int k = 0;
        for (; k + 4 <= m; k += 4) {
            int s0 = __shfl_sync(0xffffffffu, idx, k);
            int s1 = __shfl_sync(0xffffffffu, idx, k + 1);
            int s2 = __shfl_sync(0xffffffffu, idx, k + 2);
            int s3 = __shfl_sync(0xffffffffu, idx, k + 3);
            float w0 = __shfl_sync(0xffffffffu, wv, k);
            float w1 = __shfl_sync(0xffffffffu, wv, k + 1);
            float w2 = __shfl_sync(0xffffffffu, wv, k + 2);
            float w3 = __shfl_sync(0xffffffffu, wv, k + 3);
            float4 v0 = ld_row_h4(H, s0, lane);
            float4 v1 = ld_row_h4(H, s1, lane);
            float4 v2 = ld_row_h4(H, s2, lane);
            float4 v3 = ld_row_h4(H, s3, lane);
            acc.x += w0 * v0.x + w1 * v1.x + w2 * v2.x + w3 * v3.x;
            acc.y += w0 * v0.y + w1 * v1.y + w2 * v2.y + w3 * v3.y;
            acc.z += w0 * v0.z + w1 * v1.z + w2 * v2.z + w3 * v3.z;
            acc.w += w0 * v0.w + w1 * v1.w + w2 * v2.w + w3 * v3.w;
        }
        for (; k < m; k++) {
            int s0 = __shfl_sync(0xffffffffu, idx, k);
            float w0 = __shfl_sync(0xffffffffu, wv, k);
            float4 v0 = ld_row_h4(H, s0, lane);
            acc.x += w0 * v0.x;
            acc.y += w0 * v0.y;
            acc.z += w0 * v0.z;
            acc.w += w0 * v0.w;
        }
    }

    float4 b4 = ((const float4*)bias)[lane];
    float4 p  = P[(size_t)d * 32 + lane];
    float4 o;
    o.x = dd * acc.x + b4.x + p.x;
    o.y = dd * acc.y + b4.y + p.y;
    o.z = dd * acc.z + b4.z + p.z;
    o.w = dd * acc.w + b4.w + p.w;
    O[(size_t)d * 32 + lane] = o;
}

// ---------------------------------------------------------------------------
// Launch: CSR || (splitW + gemm1); then gather1(A) -> gemm2(A) on side stream
// overlapped with gather1(B); gemm2(B); gather2.
// ---------------------------------------------------------------------------
extern "C" void kernel_launch(void* const* d_in, const int* in_sizes, int n_in,
                              void* d_out, int out_size) {
    const float* x  = (const float*)d_in[0];
    const int*   ei = (const int*)  d_in[1];
    const float* pf = (const float*)d_in[2];
    const float* pl = (const float*)d_in[3];
    const float* W1 = (const float*)d_in[4];
    const float* b1 = (const float*)d_in[5];
    const float* W2 = (const float*)d_in[6];
    const float* b2 = (const float*)d_in[7];
    float* out = (float*)d_out;

    const int n = in_sizes[0] / DD;
    const int E = in_sizes[1] / 2;
    const int* src = ei;
    const int* dst = ei + E;

    __half* ph; float* pa;
    float* w1h; float* w1l; float* w2h; float* w2l;
    cudaGetSymbolAddress((void**)&ph, g_h);
    cudaGetSymbolAddress((void**)&pa, g_a);
    cudaGetSymbolAddress((void**)&w1h, g_w1h);
    cudaGetSymbolAddress((void**)&w1l, g_w1l);
    cudaGetSymbolAddress((void**)&w2h, g_w2h);
    cudaGetSymbolAddress((void**)&w2l, g_w2l);

    static cudaStream_t s2 = nullptr;
    static cudaEvent_t evFork = nullptr, evJoin = nullptr, evA = nullptr, evG2A = nullptr;
    if (!s2) {
        cudaStreamCreateWithFlags(&s2, cudaStreamNonBlocking);
        cudaEventCreateWithFlags(&evFork, cudaEventDisableTiming);
        cudaEventCreateWithFlags(&evJoin, cudaEventDisableTiming);
        cudaEventCreateWithFlags(&evA, cudaEventDisableTiming);
        cudaEventCreateWithFlags(&evG2A, cudaEventDisableTiming);
    }

    const int T = 256;
    const int nb1024 = (n + 1023) / 1024;
    const int splitw_blocks = (DD * DD + T - 1) / T;

    // Chunk split: A = [0, nA) aligned to 128-row GEMM tiles; B = [nA, n)
    const int nA = (((n + 1) / 2 + 127) / 128) * 128;
    const int nB = n - nA;

    // Fork: side stream does W splits + GEMM1 while main builds CSR.
    cudaEventRecord(evFork, 0);
    cudaStreamWaitEvent(s2, evFork, 0);

    k_split_w<<<splitw_blocks, T, 0, s2>>>(W1, w1h, w1l);
    k_split_w<<<splitw_blocks, T, 0, s2>>>(W2, w2h, w2l);
    k_gemm_tc<<<(n + 127) / 128, T, 0, s2>>>(x, w1h, w1l, ph, n);
    cudaEventRecord(evJoin, s2);

    // Main: CSR build + dinv
    k_zero_cnt<<<(n + T - 1) / T, T>>>(n);
    k_count<<<(E + T - 1) / T, T>>>(dst, E);
    k_scan1<<<nb1024, 1024>>>(n);
    k_scan2<<<1, 1024>>>(nb1024);
    k_scan3<<<nb1024, 1024>>>(n);
    k_scatter<<<(E + T - 1) / T, T>>>(src, dst, E);

    cudaStreamWaitEvent(0, evJoin, 0);

    // gather1 chunk A, then gemm2(A) on s2 concurrent with gather1 chunk B
    k_gather<<<(nA + 7) / 8, T>>>(ph, b1, (const float4*)pf, (float4*)pa, 0, nA);
    cudaEventRecord(evA, 0);
    cudaStreamWaitEvent(s2, evA, 0);
    k_gemm_tc<<<nA / 128, T, 0, s2>>>(pa, w2h, w2l, ph, nA);
    cudaEventRecord(evG2A, s2);

    k_gather<<<(nB + 7) / 8, T>>>(ph, b1, (const float4*)pf, (float4*)pa, nA, nB);
    k_gemm_tc<<<(nB + 127) / 128, T>>>(pa + (size_t)nA * 128, w2h, w2l,
                                       ph + (size_t)nA * 128, nB);
    cudaStreamWaitEvent(0, evG2A, 0);

    // Final gather over all nodes
    k_gather<<<(n + 7) / 8, T>>>(ph, b2, (const float4*)pl, (float4*)out, 0, n);
}